// round 1
// baseline (speedup 1.0000x reference)
#include <cuda_runtime.h>
#include <cuda_bf16.h>
#include <cstdint>

// Problem constants
#define DIMD 1024
#define NHEADS 16
#define HDIM 64
#define ROTD 32
#define BB 2
#define TT 32
#define HH 18
#define WW 32
#define NTOK (BB*TT*HH*WW)        // 36864
#define E3 (3*NHEADS*HDIM)        // 3072
#define TOK_TSTRIDE (HH*WW)       // 576 tokens between consecutive t

// Scratch buffers (allocation-free rule: __device__ globals)
__device__ float g_qkv[(size_t)NTOK * E3];     // ~453 MB
__device__ float g_o[(size_t)NTOK * DIMD];     // ~151 MB

// ---------------------------------------------------------------------------
// SGEMM: C[M,N] = A[M,K] * B[N,K]^T (+ bias[n]), fp32, 128x128 tile, BK=8.
// Requires M%128==0, N%128==0, K%8==0 (true for both GEMMs here).
// ---------------------------------------------------------------------------
__global__ __launch_bounds__(256) void sgemm_nt(
    const float* __restrict__ A, const float* __restrict__ B,
    const float* __restrict__ bias, float* __restrict__ C,
    int M, int N, int K)
{
    __shared__ float As[8][128];
    __shared__ float Bs[8][128];

    const int tid = threadIdx.x;
    const int m0 = blockIdx.y * 128;
    const int n0 = blockIdx.x * 128;

    const int lrow = tid >> 1;          // 0..127
    const int lcol = (tid & 1) << 2;    // 0 or 4

    const int tx = tid & 15;            // n sub-tile
    const int ty = tid >> 4;            // m sub-tile

    float acc[8][8];
#pragma unroll
    for (int i = 0; i < 8; i++)
#pragma unroll
        for (int j = 0; j < 8; j++) acc[i][j] = 0.f;

    const float* Aptr = A + (size_t)(m0 + lrow) * K + lcol;
    const float* Bptr = B + (size_t)(n0 + lrow) * K + lcol;

    for (int k0 = 0; k0 < K; k0 += 8) {
        float4 av = *(const float4*)(Aptr + k0);
        float4 bv = *(const float4*)(Bptr + k0);
        As[lcol + 0][lrow] = av.x;
        As[lcol + 1][lrow] = av.y;
        As[lcol + 2][lrow] = av.z;
        As[lcol + 3][lrow] = av.w;
        Bs[lcol + 0][lrow] = bv.x;
        Bs[lcol + 1][lrow] = bv.y;
        Bs[lcol + 2][lrow] = bv.z;
        Bs[lcol + 3][lrow] = bv.w;
        __syncthreads();

#pragma unroll
        for (int kk = 0; kk < 8; kk++) {
            float4 a0 = *(const float4*)&As[kk][ty * 4];
            float4 a1 = *(const float4*)&As[kk][64 + ty * 4];
            float4 b0 = *(const float4*)&Bs[kk][tx * 4];
            float4 b1 = *(const float4*)&Bs[kk][64 + tx * 4];
            float a[8] = {a0.x, a0.y, a0.z, a0.w, a1.x, a1.y, a1.z, a1.w};
            float b[8] = {b0.x, b0.y, b0.z, b0.w, b1.x, b1.y, b1.z, b1.w};
#pragma unroll
            for (int i = 0; i < 8; i++)
#pragma unroll
                for (int j = 0; j < 8; j++)
                    acc[i][j] = fmaf(a[i], b[j], acc[i][j]);
        }
        __syncthreads();
    }

    // Write out (two float4 stores per row-group)
#pragma unroll
    for (int i = 0; i < 8; i++) {
        int row = m0 + ((i < 4) ? (ty * 4 + i) : (64 + ty * 4 + (i - 4)));
        float* crow = C + (size_t)row * N + n0;
#pragma unroll
        for (int half = 0; half < 2; half++) {
            int cbase = half * 64 + tx * 4;
            float4 v;
            v.x = acc[i][half * 4 + 0];
            v.y = acc[i][half * 4 + 1];
            v.z = acc[i][half * 4 + 2];
            v.w = acc[i][half * 4 + 3];
            if (bias) {
                v.x += bias[n0 + cbase + 0];
                v.y += bias[n0 + cbase + 1];
                v.z += bias[n0 + cbase + 2];
                v.w += bias[n0 + cbase + 3];
            }
            *(float4*)(crow + cbase) = v;
        }
    }
}

// ---------------------------------------------------------------------------
// Attention: one block per (sequence, head). seq = (b*HH + h)*WW + w.
// Loads Q,K,V [32][64] from g_qkv, applies interleaved RoPE to first 32 dims
// of Q and K, causal softmax(QK^T * 1/8), O = P V, writes to g_o in
// (b,t,h,w, head*64+d) layout.
// ---------------------------------------------------------------------------
__global__ __launch_bounds__(128) void attn_kernel(
    const float* __restrict__ qkv, float* __restrict__ o)
{
    const int nh = blockIdx.x;
    const int head = nh & (NHEADS - 1);
    const int seq = nh >> 4;
    const int w_ = seq % WW;
    const int h_ = (seq / WW) % HH;
    const int b_ = seq / (WW * HH);
    // token(t) = ((b*TT + t)*HH + h_)*WW + w_ = base + t*TOK_TSTRIDE
    const int base = ((b_ * TT) * HH + h_) * WW + w_;

    __shared__ float Q[32][65];
    __shared__ float K[32][65];
    __shared__ float V[32][65];
    __shared__ float S[32][33];

    const int tid = threadIdx.x;

    // Load Q/K/V
    for (int idx = tid; idx < 32 * 64; idx += 128) {
        int t = idx >> 6;
        int d = idx & 63;
        size_t off = (size_t)(base + t * TOK_TSTRIDE) * E3 + head * HDIM + d;
        Q[t][d] = qkv[off];
        K[t][d] = qkv[off + NHEADS * HDIM];
        V[t][d] = qkv[off + 2 * NHEADS * HDIM];
    }
    __syncthreads();

    // RoPE on first ROTD dims of Q and K (interleaved pairs)
    const float LOG2_10000_OVER_16 = 13.287712379549449f / 16.0f;
    for (int idx = tid; idx < 32 * (ROTD / 2); idx += 128) {
        int t = idx >> 4;        // time = position
        int j = idx & 15;        // pair index 0..15
        float freq = exp2f(-(float)j * LOG2_10000_OVER_16);
        float ang = (float)t * freq;
        float c = cosf(ang), s = sinf(ang);
        float q0 = Q[t][2 * j], q1 = Q[t][2 * j + 1];
        Q[t][2 * j]     = q0 * c - q1 * s;
        Q[t][2 * j + 1] = q1 * c + q0 * s;
        float k0 = K[t][2 * j], k1 = K[t][2 * j + 1];
        K[t][2 * j]     = k0 * c - k1 * s;
        K[t][2 * j + 1] = k1 * c + k0 * s;
    }
    __syncthreads();

    // Scores S[tq][tk] = (Q[tq] . K[tk]) * scale
    for (int idx = tid; idx < 32 * 32; idx += 128) {
        int tq = idx >> 5;
        int tk = idx & 31;
        float a = 0.f;
#pragma unroll
        for (int d = 0; d < 64; d++) a = fmaf(Q[tq][d], K[tk][d], a);
        S[tq][tk] = a * 0.125f;
    }
    __syncthreads();

    // Causal softmax per row (threads 0..31, one row each)
    if (tid < 32) {
        int row = tid;
        float m = -1e30f;
        for (int k = 0; k <= row; k++) m = fmaxf(m, S[row][k]);
        float sum = 0.f;
        for (int k = 0; k <= row; k++) {
            float e = __expf(S[row][k] - m);
            S[row][k] = e;
            sum += e;
        }
        float inv = 1.0f / sum;
        for (int k = 0; k < 32; k++)
            S[row][k] = (k <= row) ? S[row][k] * inv : 0.f;
    }
    __syncthreads();

    // O = P V, write to g_o[(token), head*64 + d]
    for (int idx = tid; idx < 32 * 64; idx += 128) {
        int t = idx >> 6;
        int d = idx & 63;
        float a = 0.f;
#pragma unroll
        for (int k = 0; k < 32; k++) a = fmaf(S[t][k], V[k][d], a);
        o[(size_t)(base + t * TOK_TSTRIDE) * DIMD + head * HDIM + d] = a;
    }
}

// ---------------------------------------------------------------------------
// Launch
// ---------------------------------------------------------------------------
extern "C" void kernel_launch(void* const* d_in, const int* in_sizes, int n_in,
                              void* d_out, int out_size)
{
    const float* x     = (const float*)d_in[0];   // [NTOK, 1024]
    const float* w_qkv = (const float*)d_in[1];   // [3072, 1024]
    const float* w_out = (const float*)d_in[2];   // [1024, 1024]
    const float* b_out = (const float*)d_in[3];   // [1024]
    float* out = (float*)d_out;                   // [NTOK, 1024]

    float* qkv;
    float* o;
    cudaGetSymbolAddress((void**)&qkv, g_qkv);
    cudaGetSymbolAddress((void**)&o, g_o);

    // 1) QKV projection: [36864,1024] x [3072,1024]^T -> [36864,3072]
    {
        dim3 grid(E3 / 128, NTOK / 128);
        sgemm_nt<<<grid, 256>>>(x, w_qkv, nullptr, qkv, NTOK, E3, DIMD);
    }

    // 2) Attention per (seq, head)
    {
        int nblocks = (BB * HH * WW) * NHEADS;   // 18432
        attn_kernel<<<nblocks, 128>>>(qkv, o);
    }

    // 3) Output projection: [36864,1024] x [1024,1024]^T + bias
    {
        dim3 grid(DIMD / 128, NTOK / 128);
        sgemm_nt<<<grid, 256>>>(o, w_out, b_out, out, NTOK, DIMD, DIMD);
    }
}

// round 3
// speedup vs baseline: 2.2294x; 2.2294x over previous
#include <cuda_runtime.h>
#include <cuda_bf16.h>
#include <cstdint>

// Problem constants
#define DIMD 1024
#define NHEADS 16
#define HDIM 64
#define ROTD 32
#define BB 2
#define TT 32
#define HH 18
#define WW 32
#define NTOK (BB*TT*HH*WW)        // 36864
#define E3 (3*NHEADS*HDIM)        // 3072
#define TOK_TSTRIDE (HH*WW)       // 576

// Scratch (allocation-free rule: __device__ globals)
__device__ float g_qkv[(size_t)NTOK * E3];     // ~453 MB
__device__ float g_o[(size_t)NTOK * DIMD];     // ~151 MB

// ---------------------------------------------------------------------------
// TF32 mma.sync GEMM: C[M,N] = A[M,K] * B[N,K]^T (+bias)
// CTA tile 128x128, BK=32, 256 threads, warp tile 64x32 (m16n8k8 mma).
// M%128==0, N%128==0, K%32==0.
// ---------------------------------------------------------------------------
#define BM 128
#define BN 128
#define BK 32
#define PAD 133   // row stride in u32; makes transposed STS conflict-free

#define GSMEM_U32 (4 * BK * PAD)              // As[2] + Bs[2]
#define GSMEM_BYTES (GSMEM_U32 * 4)           // 68096 B

__device__ __forceinline__ uint32_t f2tf32(float f) {
    uint32_t r;
    asm("cvt.rna.tf32.f32 %0, %1;" : "=r"(r) : "f"(f));
    return r;
}

__device__ __forceinline__ void mma_tf32(float c[4],
                                         const uint32_t a[4], const uint32_t b[2]) {
    asm volatile(
        "mma.sync.aligned.m16n8k8.row.col.f32.tf32.tf32.f32 "
        "{%0,%1,%2,%3}, {%4,%5,%6,%7}, {%8,%9}, {%0,%1,%2,%3};"
        : "+f"(c[0]), "+f"(c[1]), "+f"(c[2]), "+f"(c[3])
        : "r"(a[0]), "r"(a[1]), "r"(a[2]), "r"(a[3]), "r"(b[0]), "r"(b[1]));
}

__global__ __launch_bounds__(256, 1) void gemm_tf32(
    const float* __restrict__ A, const float* __restrict__ B,
    const float* __restrict__ bias, float* __restrict__ C,
    int M, int N, int K)
{
    extern __shared__ uint32_t sm_[];
    uint32_t* Abase = sm_;                 // 2 buffers of BK*PAD
    uint32_t* Bbase = sm_ + 2 * BK * PAD;  // 2 buffers of BK*PAD

    const int tid = threadIdx.x;
    const int wid = tid >> 5;
    const int lid = tid & 31;
    const int g   = lid >> 2;   // group id 0..7
    const int tig = lid & 3;    // thread in group 0..3
    const int wm  = (wid >> 2) * 64;   // warp M origin: 0 or 64
    const int wn  = (wid & 3) * 32;    // warp N origin: 0,32,64,96
    const int m0 = blockIdx.y * BM;
    const int n0 = blockIdx.x * BN;

    // Global load mapping: f4 index i = tid + j*256, row = i>>3 (0..127), kc4 = i&7
    int row_[4], kc4_[4];
#pragma unroll
    for (int j = 0; j < 4; j++) {
        int i = tid + j * 256;
        row_[j] = i >> 3;
        kc4_[j] = i & 7;
    }

    const float4* A4 = (const float4*)A;
    const float4* B4 = (const float4*)B;
    const int K4 = K >> 2;

    float acc[4][4][4];
#pragma unroll
    for (int mt = 0; mt < 4; mt++)
#pragma unroll
        for (int nt = 0; nt < 4; nt++)
#pragma unroll
            for (int e = 0; e < 4; e++) acc[mt][nt][e] = 0.f;

    float4 av[4], bv[4];

    // Prologue: load chunk 0, convert+store to buffer 0
#pragma unroll
    for (int j = 0; j < 4; j++) {
        av[j] = A4[(size_t)(m0 + row_[j]) * K4 + kc4_[j]];
        bv[j] = B4[(size_t)(n0 + row_[j]) * K4 + kc4_[j]];
    }
    {
        uint32_t* as = Abase;
        uint32_t* bs = Bbase;
#pragma unroll
        for (int j = 0; j < 4; j++) {
            int kb = kc4_[j] * 4;
            as[(kb + 0) * PAD + row_[j]] = f2tf32(av[j].x);
            as[(kb + 1) * PAD + row_[j]] = f2tf32(av[j].y);
            as[(kb + 2) * PAD + row_[j]] = f2tf32(av[j].z);
            as[(kb + 3) * PAD + row_[j]] = f2tf32(av[j].w);
            bs[(kb + 0) * PAD + row_[j]] = f2tf32(bv[j].x);
            bs[(kb + 1) * PAD + row_[j]] = f2tf32(bv[j].y);
            bs[(kb + 2) * PAD + row_[j]] = f2tf32(bv[j].z);
            bs[(kb + 3) * PAD + row_[j]] = f2tf32(bv[j].w);
        }
    }
    __syncthreads();

    const int NC = K / BK;
    for (int c = 0; c < NC; c++) {
        const int buf = c & 1;

        // Prefetch next chunk to registers
        if (c + 1 < NC) {
            const int kb4 = (c + 1) * (BK / 4);
#pragma unroll
            for (int j = 0; j < 4; j++) {
                av[j] = A4[(size_t)(m0 + row_[j]) * K4 + kb4 + kc4_[j]];
                bv[j] = B4[(size_t)(n0 + row_[j]) * K4 + kb4 + kc4_[j]];
            }
        }

        // Compute on current buffer
        const uint32_t* as = Abase + buf * BK * PAD;
        const uint32_t* bs = Bbase + buf * BK * PAD;
#pragma unroll
        for (int kk = 0; kk < BK; kk += 8) {
            uint32_t af[4][4], bf[4][2];
#pragma unroll
            for (int mt = 0; mt < 4; mt++) {
                int mr = wm + mt * 16 + g;
                af[mt][0] = as[(kk + tig) * PAD + mr];
                af[mt][1] = as[(kk + tig) * PAD + mr + 8];
                af[mt][2] = as[(kk + tig + 4) * PAD + mr];
                af[mt][3] = as[(kk + tig + 4) * PAD + mr + 8];
            }
#pragma unroll
            for (int nt = 0; nt < 4; nt++) {
                int nc_ = wn + nt * 8 + g;
                bf[nt][0] = bs[(kk + tig) * PAD + nc_];
                bf[nt][1] = bs[(kk + tig + 4) * PAD + nc_];
            }
#pragma unroll
            for (int mt = 0; mt < 4; mt++)
#pragma unroll
                for (int nt = 0; nt < 4; nt++)
                    mma_tf32(acc[mt][nt], af[mt], bf[nt]);
        }

        // Store prefetched chunk into the other buffer
        if (c + 1 < NC) {
            uint32_t* as2 = Abase + (buf ^ 1) * BK * PAD;
            uint32_t* bs2 = Bbase + (buf ^ 1) * BK * PAD;
#pragma unroll
            for (int j = 0; j < 4; j++) {
                int kb = kc4_[j] * 4;
                as2[(kb + 0) * PAD + row_[j]] = f2tf32(av[j].x);
                as2[(kb + 1) * PAD + row_[j]] = f2tf32(av[j].y);
                as2[(kb + 2) * PAD + row_[j]] = f2tf32(av[j].z);
                as2[(kb + 3) * PAD + row_[j]] = f2tf32(av[j].w);
                bs2[(kb + 0) * PAD + row_[j]] = f2tf32(bv[j].x);
                bs2[(kb + 1) * PAD + row_[j]] = f2tf32(bv[j].y);
                bs2[(kb + 2) * PAD + row_[j]] = f2tf32(bv[j].z);
                bs2[(kb + 3) * PAD + row_[j]] = f2tf32(bv[j].w);
            }
        }
        __syncthreads();
    }

    // Epilogue: write C (+bias)
#pragma unroll
    for (int mt = 0; mt < 4; mt++) {
        const int r = m0 + wm + mt * 16 + g;
#pragma unroll
        for (int nt = 0; nt < 4; nt++) {
            const int ccol = n0 + wn + nt * 8 + tig * 2;
            float b0v = 0.f, b1v = 0.f;
            if (bias) { b0v = __ldg(bias + ccol); b1v = __ldg(bias + ccol + 1); }
            float2 v;
            v.x = acc[mt][nt][0] + b0v;
            v.y = acc[mt][nt][1] + b1v;
            *(float2*)&C[(size_t)r * N + ccol] = v;
            v.x = acc[mt][nt][2] + b0v;
            v.y = acc[mt][nt][3] + b1v;
            *(float2*)&C[(size_t)(r + 8) * N + ccol] = v;
        }
    }
}

// ---------------------------------------------------------------------------
// Attention: one block per (sequence, head) — unchanged (correct, ~minor cost).
// ---------------------------------------------------------------------------
__global__ __launch_bounds__(128) void attn_kernel(
    const float* __restrict__ qkv, float* __restrict__ o)
{
    const int nh = blockIdx.x;
    const int head = nh & (NHEADS - 1);
    const int seq = nh >> 4;
    const int w_ = seq % WW;
    const int h_ = (seq / WW) % HH;
    const int b_ = seq / (WW * HH);
    const int base = ((b_ * TT) * HH + h_) * WW + w_;

    __shared__ float Q[32][65];
    __shared__ float K[32][65];
    __shared__ float V[32][65];
    __shared__ float S[32][33];

    const int tid = threadIdx.x;

    for (int idx = tid; idx < 32 * 64; idx += 128) {
        int t = idx >> 6;
        int d = idx & 63;
        size_t off = (size_t)(base + t * TOK_TSTRIDE) * E3 + head * HDIM + d;
        Q[t][d] = qkv[off];
        K[t][d] = qkv[off + NHEADS * HDIM];
        V[t][d] = qkv[off + 2 * NHEADS * HDIM];
    }
    __syncthreads();

    const float LOG2_10000_OVER_16 = 13.287712379549449f / 16.0f;
    for (int idx = tid; idx < 32 * (ROTD / 2); idx += 128) {
        int t = idx >> 4;
        int j = idx & 15;
        float freq = exp2f(-(float)j * LOG2_10000_OVER_16);
        float ang = (float)t * freq;
        float c = cosf(ang), s = sinf(ang);
        float q0 = Q[t][2 * j], q1 = Q[t][2 * j + 1];
        Q[t][2 * j]     = q0 * c - q1 * s;
        Q[t][2 * j + 1] = q1 * c + q0 * s;
        float k0 = K[t][2 * j], k1 = K[t][2 * j + 1];
        K[t][2 * j]     = k0 * c - k1 * s;
        K[t][2 * j + 1] = k1 * c + k0 * s;
    }
    __syncthreads();

    for (int idx = tid; idx < 32 * 32; idx += 128) {
        int tq = idx >> 5;
        int tk = idx & 31;
        float a = 0.f;
#pragma unroll
        for (int d = 0; d < 64; d++) a = fmaf(Q[tq][d], K[tk][d], a);
        S[tq][tk] = a * 0.125f;
    }
    __syncthreads();

    if (tid < 32) {
        int row = tid;
        float m = -1e30f;
        for (int k = 0; k <= row; k++) m = fmaxf(m, S[row][k]);
        float sum = 0.f;
        for (int k = 0; k <= row; k++) {
            float e = __expf(S[row][k] - m);
            S[row][k] = e;
            sum += e;
        }
        float inv = 1.0f / sum;
        for (int k = 0; k < 32; k++)
            S[row][k] = (k <= row) ? S[row][k] * inv : 0.f;
    }
    __syncthreads();

    for (int idx = tid; idx < 32 * 64; idx += 128) {
        int t = idx >> 6;
        int d = idx & 63;
        float a = 0.f;
#pragma unroll
        for (int k = 0; k < 32; k++) a = fmaf(S[t][k], V[k][d], a);
        o[(size_t)(base + t * TOK_TSTRIDE) * DIMD + head * HDIM + d] = a;
    }
}

// ---------------------------------------------------------------------------
// Launch
// ---------------------------------------------------------------------------
extern "C" void kernel_launch(void* const* d_in, const int* in_sizes, int n_in,
                              void* d_out, int out_size)
{
    const float* x     = (const float*)d_in[0];   // [NTOK, 1024]
    const float* w_qkv = (const float*)d_in[1];   // [3072, 1024]
    const float* w_out = (const float*)d_in[2];   // [1024, 1024]
    const float* b_out = (const float*)d_in[3];   // [1024]
    float* out = (float*)d_out;                   // [NTOK, 1024]

    float* qkv;
    float* o;
    cudaGetSymbolAddress((void**)&qkv, g_qkv);
    cudaGetSymbolAddress((void**)&o, g_o);

    cudaFuncSetAttribute(gemm_tf32, cudaFuncAttributeMaxDynamicSharedMemorySize, GSMEM_BYTES);

    // 1) QKV projection: [36864,1024] x [3072,1024]^T -> [36864,3072]
    {
        dim3 grid(E3 / 128, NTOK / 128);
        gemm_tf32<<<grid, 256, GSMEM_BYTES>>>(x, w_qkv, nullptr, qkv, NTOK, E3, DIMD);
    }

    // 2) Attention
    {
        int nblocks = (BB * HH * WW) * NHEADS;   // 18432
        attn_kernel<<<nblocks, 128>>>(qkv, o);
    }

    // 3) Output projection: [36864,1024] x [1024,1024]^T + bias
    {
        dim3 grid(DIMD / 128, NTOK / 128);
        gemm_tf32<<<grid, 256, GSMEM_BYTES>>>(o, w_out, b_out, out, NTOK, DIMD, DIMD);
    }
}

// round 5
// speedup vs baseline: 3.2853x; 1.4736x over previous
#include <cuda_runtime.h>
#include <cuda_bf16.h>
#include <cstdint>

// Problem constants
#define DIMD 1024
#define NHEADS 16
#define HDIM 64
#define ROTD 32
#define BB 2
#define TT 32
#define HH 18
#define WW 32
#define NTOK (BB*TT*HH*WW)        // 36864
#define E3 (3*NHEADS*HDIM)        // 3072
#define TOK_TSTRIDE (HH*WW)       // 576

// Scratch (__device__ globals; allocation-free rule)
__device__ float    g_qkv[(size_t)NTOK * E3];     // fp32 qkv (attention input)
__device__ uint32_t g_o[(size_t)NTOK * DIMD];     // attention output, tf32 bits
__device__ uint32_t g_xt[(size_t)NTOK * DIMD];    // x converted to tf32 bits
__device__ uint32_t g_wqt[(size_t)E3 * DIMD];     // w_qkv tf32 bits
__device__ uint32_t g_wot[(size_t)DIMD * DIMD];   // w_out tf32 bits

// ---------------------------------------------------------------------------
// Helpers
// ---------------------------------------------------------------------------
__device__ __forceinline__ uint32_t smem_u32(const void* p) {
    uint32_t a;
    asm("{ .reg .u64 t; cvta.to.shared.u64 t, %1; cvt.u32.u64 %0, t; }" : "=r"(a) : "l"(p));
    return a;
}
__device__ __forceinline__ uint32_t f2tf32(float f) {
    uint32_t r;
    asm("cvt.rna.tf32.f32 %0, %1;" : "=r"(r) : "f"(f));
    return r;
}
__device__ __forceinline__ void cp16(uint32_t saddr, const void* gaddr) {
    asm volatile("cp.async.cg.shared.global [%0], [%1], 16;" :: "r"(saddr), "l"(gaddr));
}
__device__ __forceinline__ void cp_commit() {
    asm volatile("cp.async.commit_group;" ::: "memory");
}
template <int N>
__device__ __forceinline__ void cp_wait() {
    asm volatile("cp.async.wait_group %0;" :: "n"(N) : "memory");
}
__device__ __forceinline__ void ldsm4(uint32_t* r, uint32_t addr) {
    asm volatile("ldmatrix.sync.aligned.m8n8.x4.shared.b16 {%0,%1,%2,%3}, [%4];"
                 : "=r"(r[0]), "=r"(r[1]), "=r"(r[2]), "=r"(r[3]) : "r"(addr));
}
__device__ __forceinline__ void mma_tf32(float c[4],
                                         const uint32_t a[4], const uint32_t b[2]) {
    asm volatile(
        "mma.sync.aligned.m16n8k8.row.col.f32.tf32.tf32.f32 "
        "{%0,%1,%2,%3}, {%4,%5,%6,%7}, {%8,%9}, {%0,%1,%2,%3};"
        : "+f"(c[0]), "+f"(c[1]), "+f"(c[2]), "+f"(c[3])
        : "r"(a[0]), "r"(a[1]), "r"(a[2]), "r"(a[3]), "r"(b[0]), "r"(b[1]));
}

// ---------------------------------------------------------------------------
// Elementwise fp32 -> tf32-bits (rna) converter. n in float4 units.
// ---------------------------------------------------------------------------
__global__ __launch_bounds__(256) void cvt_tf32(const float4* __restrict__ in,
                                                uint4* __restrict__ out, int n4)
{
    int i = blockIdx.x * 256 + threadIdx.x;
    if (i < n4) {
        float4 v = in[i];
        uint4 o;
        o.x = f2tf32(v.x); o.y = f2tf32(v.y); o.z = f2tf32(v.z); o.w = f2tf32(v.w);
        out[i] = o;
    }
}

// ---------------------------------------------------------------------------
// TF32 GEMM: C[M,N] = A[M,K] * B[N,K]^T (+bias). A,B hold tf32 bits.
// CTA 128x128, BK=32, 128 threads (4 warps, 64x64 warp tile), cp.async 2-stage,
// ldmatrix fragments, m16n8k8 tf32 mma.
// ---------------------------------------------------------------------------
#define LDSK 36                          // u32 row stride (32 data + 4 pad)
#define STAGE_U32 (128 * LDSK)           // 4608 u32 per matrix per stage
#define STAGE_BYTES (STAGE_U32 * 4)      // 18432
#define PAIR_BYTES (2 * STAGE_BYTES)     // A+B per stage = 36864
#define GSMEM_BYTES (2 * PAIR_BYTES)     // 73728

__global__ __launch_bounds__(128, 2) void gemm_tf32(
    const uint32_t* __restrict__ A, const uint32_t* __restrict__ B,
    const float* __restrict__ bias, float* __restrict__ C,
    int M, int N, int K)
{
    extern __shared__ uint32_t sm_[];
    const uint32_t sbase = smem_u32(sm_);

    const int tid = threadIdx.x;
    const int wid = tid >> 5;
    const int lid = tid & 31;
    const int g   = lid >> 2;
    const int tig = lid & 3;
    const int wm  = (wid >> 1) * 64;
    const int wn  = (wid & 1) * 64;
    const int m0 = blockIdx.y * 128;
    const int n0 = blockIdx.x * 128;

    const int K4 = K >> 2;
    const uint4* A4 = (const uint4*)A;
    const uint4* B4 = (const uint4*)B;

    // Loader mapping: chunk i = tid + j*128 -> row = i>>3, kc4 = i&7
    const int lsub = tid >> 3;   // 0..15
    const int lkc4 = tid & 7;

    // Fragment lane offsets (u32 units within a stage matrix)
    const int a_lane = ((lid & 7) + ((lid >> 3) & 1) * 8) * LDSK + ((lid >> 4) & 1) * 4;
    const int b_lane = ((lid & 7) + ((lid >> 4) & 1) * 8) * LDSK + ((lid >> 3) & 1) * 4;
    const uint32_t aoff = (uint32_t)(wm * LDSK + a_lane) * 4;  // bytes
    const uint32_t boff = (uint32_t)(wn * LDSK + b_lane) * 4;

    float acc[4][8][4];
#pragma unroll
    for (int mt = 0; mt < 4; mt++)
#pragma unroll
        for (int nt = 0; nt < 8; nt++)
#pragma unroll
            for (int e = 0; e < 4; e++) acc[mt][nt][e] = 0.f;

    const int NC = K >> 5;   // K/32

    // ---- stage loader ----
    auto load_stage = [&](int s, int c) {
        const uint32_t abase = sbase + s * PAIR_BYTES;
        const uint32_t bbase = abase + STAGE_BYTES;
        const int kb4 = c * 8;  // uint4 offset along K
#pragma unroll
        for (int j = 0; j < 8; j++) {
            const int row = j * 16 + lsub;
            const uint32_t soff = (uint32_t)(row * LDSK + lkc4 * 4) * 4;
            cp16(abase + soff, A4 + (size_t)(m0 + row) * K4 + kb4 + lkc4);
            cp16(bbase + soff, B4 + (size_t)(n0 + row) * K4 + kb4 + lkc4);
        }
    };

    // Prologue: two stages in flight
    load_stage(0, 0);
    cp_commit();
    if (NC > 1) load_stage(1, 1);
    cp_commit();

    for (int c = 0; c < NC; c++) {
        cp_wait<1>();
        __syncthreads();

        const int s = c & 1;
        const uint32_t abase = sbase + s * PAIR_BYTES;
        const uint32_t bbase = abase + STAGE_BYTES;

#pragma unroll
        for (int kk = 0; kk < 32; kk += 8) {
            uint32_t af[4][4];
            uint32_t bf[8][2];
#pragma unroll
            for (int mt = 0; mt < 4; mt++)
                ldsm4(af[mt], abase + aoff + (uint32_t)(mt * 16 * LDSK + kk) * 4);
#pragma unroll
            for (int p = 0; p < 4; p++)
                ldsm4(&bf[2 * p][0], bbase + boff + (uint32_t)(p * 16 * LDSK + kk) * 4);
#pragma unroll
            for (int mt = 0; mt < 4; mt++)
#pragma unroll
                for (int nt = 0; nt < 8; nt++)
                    mma_tf32(acc[mt][nt], af[mt], bf[nt]);
        }
        __syncthreads();

        if (c + 2 < NC) load_stage(s, c + 2);
        cp_commit();   // real or empty group: keeps wait<1> semantics exact
    }

    // Epilogue
#pragma unroll
    for (int mt = 0; mt < 4; mt++) {
        const int r = m0 + wm + mt * 16 + g;
#pragma unroll
        for (int nt = 0; nt < 8; nt++) {
            const int ccol = n0 + wn + nt * 8 + tig * 2;
            float b0v = 0.f, b1v = 0.f;
            if (bias) { b0v = __ldg(bias + ccol); b1v = __ldg(bias + ccol + 1); }
            float2 v;
            v.x = acc[mt][nt][0] + b0v;
            v.y = acc[mt][nt][1] + b1v;
            *(float2*)&C[(size_t)r * N + ccol] = v;
            v.x = acc[mt][nt][2] + b0v;
            v.y = acc[mt][nt][3] + b1v;
            *(float2*)&C[(size_t)(r + 8) * N + ccol] = v;
        }
    }
}

// ---------------------------------------------------------------------------
// Attention: one block per (sequence, head). Output written as tf32 bits
// (feeds GEMM2 directly).
// ---------------------------------------------------------------------------
__global__ __launch_bounds__(128) void attn_kernel(
    const float* __restrict__ qkv, uint32_t* __restrict__ o)
{
    const int nh = blockIdx.x;
    const int head = nh & (NHEADS - 1);
    const int seq = nh >> 4;
    const int w_ = seq % WW;
    const int h_ = (seq / WW) % HH;
    const int b_ = seq / (WW * HH);
    const int base = ((b_ * TT) * HH + h_) * WW + w_;

    __shared__ float Q[32][65];
    __shared__ float K[32][65];
    __shared__ float V[32][65];
    __shared__ float S[32][33];

    const int tid = threadIdx.x;

    for (int idx = tid; idx < 32 * 64; idx += 128) {
        int t = idx >> 6;
        int d = idx & 63;
        size_t off = (size_t)(base + t * TOK_TSTRIDE) * E3 + head * HDIM + d;
        Q[t][d] = qkv[off];
        K[t][d] = qkv[off + NHEADS * HDIM];
        V[t][d] = qkv[off + 2 * NHEADS * HDIM];
    }
    __syncthreads();

    const float LOG2_10000_OVER_16 = 13.287712379549449f / 16.0f;
    for (int idx = tid; idx < 32 * (ROTD / 2); idx += 128) {
        int t = idx >> 4;
        int j = idx & 15;
        float freq = exp2f(-(float)j * LOG2_10000_OVER_16);
        float ang = (float)t * freq;
        float c = cosf(ang), s = sinf(ang);
        float q0 = Q[t][2 * j], q1 = Q[t][2 * j + 1];
        Q[t][2 * j]     = q0 * c - q1 * s;
        Q[t][2 * j + 1] = q1 * c + q0 * s;
        float k0 = K[t][2 * j], k1 = K[t][2 * j + 1];
        K[t][2 * j]     = k0 * c - k1 * s;
        K[t][2 * j + 1] = k1 * c + k0 * s;
    }
    __syncthreads();

    for (int idx = tid; idx < 32 * 32; idx += 128) {
        int tq = idx >> 5;
        int tk = idx & 31;
        float a = 0.f;
#pragma unroll
        for (int d = 0; d < 64; d++) a = fmaf(Q[tq][d], K[tk][d], a);
        S[tq][tk] = a * 0.125f;
    }
    __syncthreads();

    if (tid < 32) {
        int row = tid;
        float m = -1e30f;
        for (int k = 0; k <= row; k++) m = fmaxf(m, S[row][k]);
        float sum = 0.f;
        for (int k = 0; k <= row; k++) {
            float e = __expf(S[row][k] - m);
            S[row][k] = e;
            sum += e;
        }
        float inv = 1.0f / sum;
        for (int k = 0; k < 32; k++)
            S[row][k] = (k <= row) ? S[row][k] * inv : 0.f;
    }
    __syncthreads();

    for (int idx = tid; idx < 32 * 64; idx += 128) {
        int t = idx >> 6;
        int d = idx & 63;
        float a = 0.f;
#pragma unroll
        for (int k = 0; k < 32; k++) a = fmaf(S[t][k], V[k][d], a);
        o[(size_t)(base + t * TOK_TSTRIDE) * DIMD + head * HDIM + d] = f2tf32(a);
    }
}

// ---------------------------------------------------------------------------
// Launch
// ---------------------------------------------------------------------------
extern "C" void kernel_launch(void* const* d_in, const int* in_sizes, int n_in,
                              void* d_out, int out_size)
{
    const float* x     = (const float*)d_in[0];   // [NTOK, 1024]
    const float* w_qkv = (const float*)d_in[1];   // [3072, 1024]
    const float* w_out = (const float*)d_in[2];   // [1024, 1024]
    const float* b_out = (const float*)d_in[3];   // [1024]
    float* out = (float*)d_out;                   // [NTOK, 1024]

    float* qkv;   uint32_t* o;
    uint32_t* xt; uint32_t* wqt; uint32_t* wot;
    cudaGetSymbolAddress((void**)&qkv, g_qkv);
    cudaGetSymbolAddress((void**)&o,   g_o);
    cudaGetSymbolAddress((void**)&xt,  g_xt);
    cudaGetSymbolAddress((void**)&wqt, g_wqt);
    cudaGetSymbolAddress((void**)&wot, g_wot);

    cudaFuncSetAttribute(gemm_tf32, cudaFuncAttributeMaxDynamicSharedMemorySize, GSMEM_BYTES);

    // 0) Convert inputs to tf32 bits (rna)
    {
        int n4 = NTOK * DIMD / 4;
        cvt_tf32<<<(n4 + 255) / 256, 256>>>((const float4*)x, (uint4*)xt, n4);
        n4 = E3 * DIMD / 4;
        cvt_tf32<<<(n4 + 255) / 256, 256>>>((const float4*)w_qkv, (uint4*)wqt, n4);
        n4 = DIMD * DIMD / 4;
        cvt_tf32<<<(n4 + 255) / 256, 256>>>((const float4*)w_out, (uint4*)wot, n4);
    }

    // 1) QKV projection: [36864,1024] x [3072,1024]^T -> [36864,3072] (fp32 out)
    {
        dim3 grid(E3 / 128, NTOK / 128);
        gemm_tf32<<<grid, 128, GSMEM_BYTES>>>(xt, wqt, nullptr, qkv, NTOK, E3, DIMD);
    }

    // 2) Attention (writes tf32-bit output)
    {
        int nblocks = (BB * HH * WW) * NHEADS;   // 18432
        attn_kernel<<<nblocks, 128>>>(qkv, o);
    }

    // 3) Output projection: [36864,1024] x [1024,1024]^T + bias
    {
        dim3 grid(DIMD / 128, NTOK / 128);
        gemm_tf32<<<grid, 128, GSMEM_BYTES>>>(o, wot, b_out, out, NTOK, DIMD, DIMD);
    }
}

// round 6
// speedup vs baseline: 3.3975x; 1.0341x over previous
#include <cuda_runtime.h>
#include <cuda_bf16.h>
#include <cstdint>

// Problem constants
#define DIMD 1024
#define NHEADS 16
#define HDIM 64
#define ROTD 32
#define BB 2
#define TT 32
#define HH 18
#define WW 32
#define NTOK (BB*TT*HH*WW)        // 36864
#define E3 (3*NHEADS*HDIM)        // 3072
#define TOK_TSTRIDE (HH*WW)       // 576

// Scratch (__device__ globals; allocation-free rule)
__device__ float    g_qkv[(size_t)NTOK * E3];     // fp32 qkv (attention input)
__device__ uint32_t g_o[(size_t)NTOK * DIMD];     // attention output, tf32 bits
__device__ uint32_t g_xt[(size_t)NTOK * DIMD];    // x converted to tf32 bits
__device__ uint32_t g_wqt[(size_t)E3 * DIMD];     // w_qkv tf32 bits
__device__ uint32_t g_wot[(size_t)DIMD * DIMD];   // w_out tf32 bits

// ---------------------------------------------------------------------------
// Helpers
// ---------------------------------------------------------------------------
__device__ __forceinline__ uint32_t smem_u32(const void* p) {
    uint32_t a;
    asm("{ .reg .u64 t; cvta.to.shared.u64 t, %1; cvt.u32.u64 %0, t; }" : "=r"(a) : "l"(p));
    return a;
}
__device__ __forceinline__ uint32_t f2tf32(float f) {
    uint32_t r;
    asm("cvt.rna.tf32.f32 %0, %1;" : "=r"(r) : "f"(f));
    return r;
}
__device__ __forceinline__ void cp16(uint32_t saddr, const void* gaddr) {
    asm volatile("cp.async.cg.shared.global [%0], [%1], 16;" :: "r"(saddr), "l"(gaddr));
}
__device__ __forceinline__ void cp_commit() {
    asm volatile("cp.async.commit_group;" ::: "memory");
}
template <int N>
__device__ __forceinline__ void cp_wait() {
    asm volatile("cp.async.wait_group %0;" :: "n"(N) : "memory");
}
__device__ __forceinline__ void ldsm4(uint32_t* r, uint32_t addr) {
    asm volatile("ldmatrix.sync.aligned.m8n8.x4.shared.b16 {%0,%1,%2,%3}, [%4];"
                 : "=r"(r[0]), "=r"(r[1]), "=r"(r[2]), "=r"(r[3]) : "r"(addr));
}
__device__ __forceinline__ void mma_tf32(float c[4],
                                         const uint32_t a[4], const uint32_t b[2]) {
    asm volatile(
        "mma.sync.aligned.m16n8k8.row.col.f32.tf32.tf32.f32 "
        "{%0,%1,%2,%3}, {%4,%5,%6,%7}, {%8,%9}, {%0,%1,%2,%3};"
        : "+f"(c[0]), "+f"(c[1]), "+f"(c[2]), "+f"(c[3])
        : "r"(a[0]), "r"(a[1]), "r"(a[2]), "r"(a[3]), "r"(b[0]), "r"(b[1]));
}

// ---------------------------------------------------------------------------
// Elementwise fp32 -> tf32-bits (rna) converter. n in float4 units.
// ---------------------------------------------------------------------------
__global__ __launch_bounds__(256) void cvt_tf32(const float4* __restrict__ in,
                                                uint4* __restrict__ out, int n4)
{
    int i = blockIdx.x * 256 + threadIdx.x;
    if (i < n4) {
        float4 v = in[i];
        uint4 o;
        o.x = f2tf32(v.x); o.y = f2tf32(v.y); o.z = f2tf32(v.z); o.w = f2tf32(v.w);
        out[i] = o;
    }
}

// ---------------------------------------------------------------------------
// TF32 GEMM: C[M,N] = A[M,K] * B[N,K]^T (+bias). A,B hold tf32 bits.
// CTA 128x128, BK=32, 128 threads (4 warps, 64x64 warp tile),
// 3-stage cp.async pipeline (single __syncthreads per iter), ldmatrix,
// m16n8k8 tf32 mma.
// ---------------------------------------------------------------------------
#define NSTAGE 3
#define LDSK 36                          // u32 row stride (32 data + 4 pad)
#define STAGE_U32 (128 * LDSK)           // 4608 u32 per matrix per stage
#define STAGE_BYTES (STAGE_U32 * 4)      // 18432
#define PAIR_BYTES (2 * STAGE_BYTES)     // A+B per stage = 36864
#define GSMEM_BYTES (NSTAGE * PAIR_BYTES) // 110592

__global__ __launch_bounds__(128, 2) void gemm_tf32(
    const uint32_t* __restrict__ A, const uint32_t* __restrict__ B,
    const float* __restrict__ bias, float* __restrict__ C,
    int M, int N, int K)
{
    extern __shared__ uint32_t sm_[];
    const uint32_t sbase = smem_u32(sm_);

    const int tid = threadIdx.x;
    const int wid = tid >> 5;
    const int lid = tid & 31;
    const int g   = lid >> 2;
    const int tig = lid & 3;
    const int wm  = (wid >> 1) * 64;
    const int wn  = (wid & 1) * 64;
    const int m0 = blockIdx.y * 128;
    const int n0 = blockIdx.x * 128;

    const int K4 = K >> 2;
    const uint4* A4 = (const uint4*)A;
    const uint4* B4 = (const uint4*)B;

    // Loader mapping: chunk i = tid + j*128 -> row = i>>3, kc4 = i&7
    const int lsub = tid >> 3;   // 0..15
    const int lkc4 = tid & 7;

    // Fragment lane offsets (u32 units within a stage matrix)
    const int a_lane = ((lid & 7) + ((lid >> 3) & 1) * 8) * LDSK + ((lid >> 4) & 1) * 4;
    const int b_lane = ((lid & 7) + ((lid >> 4) & 1) * 8) * LDSK + ((lid >> 3) & 1) * 4;
    const uint32_t aoff = (uint32_t)(wm * LDSK + a_lane) * 4;  // bytes
    const uint32_t boff = (uint32_t)(wn * LDSK + b_lane) * 4;

    float acc[4][8][4];
#pragma unroll
    for (int mt = 0; mt < 4; mt++)
#pragma unroll
        for (int nt = 0; nt < 8; nt++)
#pragma unroll
            for (int e = 0; e < 4; e++) acc[mt][nt][e] = 0.f;

    const int NC = K >> 5;   // K/32

    // ---- stage loader: loads K-chunk c into ring buffer slot s ----
    auto load_stage = [&](int s, int c) {
        const uint32_t abase = sbase + s * PAIR_BYTES;
        const uint32_t bbase = abase + STAGE_BYTES;
        const int kb4 = c * 8;  // uint4 offset along K
#pragma unroll
        for (int j = 0; j < 8; j++) {
            const int row = j * 16 + lsub;
            const uint32_t soff = (uint32_t)(row * LDSK + lkc4 * 4) * 4;
            cp16(abase + soff, A4 + (size_t)(m0 + row) * K4 + kb4 + lkc4);
            cp16(bbase + soff, B4 + (size_t)(n0 + row) * K4 + kb4 + lkc4);
        }
    };

    // Prologue: NSTAGE-1 stages in flight
    load_stage(0, 0);
    cp_commit();
    load_stage(1, 1);
    cp_commit();

    for (int c = 0; c < NC; c++) {
        // Stage c must be resident: allow 1 outstanding group (stage c+1)
        cp_wait<1>();
        __syncthreads();   // all warps done reading buffer (c-1)%NSTAGE too

        // Issue load for stage c+2 into slot (c+2)%NSTAGE == (c-1)%NSTAGE
        if (c + 2 < NC) load_stage((c + 2) % NSTAGE, c + 2);
        cp_commit();       // exactly one group per iteration (may be empty)

        const int s = c % NSTAGE;
        const uint32_t abase = sbase + s * PAIR_BYTES;
        const uint32_t bbase = abase + STAGE_BYTES;

#pragma unroll
        for (int kk = 0; kk < 32; kk += 8) {
            uint32_t af[4][4];
            uint32_t bf[8][2];
#pragma unroll
            for (int mt = 0; mt < 4; mt++)
                ldsm4(af[mt], abase + aoff + (uint32_t)(mt * 16 * LDSK + kk) * 4);
#pragma unroll
            for (int p = 0; p < 4; p++)
                ldsm4(&bf[2 * p][0], bbase + boff + (uint32_t)(p * 16 * LDSK + kk) * 4);
#pragma unroll
            for (int mt = 0; mt < 4; mt++)
#pragma unroll
                for (int nt = 0; nt < 8; nt++)
                    mma_tf32(acc[mt][nt], af[mt], bf[nt]);
        }
        // no trailing barrier: next iteration's __syncthreads (after cp_wait)
        // orders readers of this buffer against its overwrite two iters later
    }

    // Epilogue
#pragma unroll
    for (int mt = 0; mt < 4; mt++) {
        const int r = m0 + wm + mt * 16 + g;
#pragma unroll
        for (int nt = 0; nt < 8; nt++) {
            const int ccol = n0 + wn + nt * 8 + tig * 2;
            float b0v = 0.f, b1v = 0.f;
            if (bias) { b0v = __ldg(bias + ccol); b1v = __ldg(bias + ccol + 1); }
            float2 v;
            v.x = acc[mt][nt][0] + b0v;
            v.y = acc[mt][nt][1] + b1v;
            *(float2*)&C[(size_t)r * N + ccol] = v;
            v.x = acc[mt][nt][2] + b0v;
            v.y = acc[mt][nt][3] + b1v;
            *(float2*)&C[(size_t)(r + 8) * N + ccol] = v;
        }
    }
}

// ---------------------------------------------------------------------------
// Attention: one block per (sequence, head). Output written as tf32 bits
// (feeds GEMM2 directly).
// ---------------------------------------------------------------------------
__global__ __launch_bounds__(128) void attn_kernel(
    const float* __restrict__ qkv, uint32_t* __restrict__ o)
{
    const int nh = blockIdx.x;
    const int head = nh & (NHEADS - 1);
    const int seq = nh >> 4;
    const int w_ = seq % WW;
    const int h_ = (seq / WW) % HH;
    const int b_ = seq / (WW * HH);
    const int base = ((b_ * TT) * HH + h_) * WW + w_;

    __shared__ float Q[32][65];
    __shared__ float K[32][65];
    __shared__ float V[32][65];
    __shared__ float S[32][33];

    const int tid = threadIdx.x;

    for (int idx = tid; idx < 32 * 64; idx += 128) {
        int t = idx >> 6;
        int d = idx & 63;
        size_t off = (size_t)(base + t * TOK_TSTRIDE) * E3 + head * HDIM + d;
        Q[t][d] = qkv[off];
        K[t][d] = qkv[off + NHEADS * HDIM];
        V[t][d] = qkv[off + 2 * NHEADS * HDIM];
    }
    __syncthreads();

    const float LOG2_10000_OVER_16 = 13.287712379549449f / 16.0f;
    for (int idx = tid; idx < 32 * (ROTD / 2); idx += 128) {
        int t = idx >> 4;
        int j = idx & 15;
        float freq = exp2f(-(float)j * LOG2_10000_OVER_16);
        float ang = (float)t * freq;
        float c = cosf(ang), s = sinf(ang);
        float q0 = Q[t][2 * j], q1 = Q[t][2 * j + 1];
        Q[t][2 * j]     = q0 * c - q1 * s;
        Q[t][2 * j + 1] = q1 * c + q0 * s;
        float k0 = K[t][2 * j], k1 = K[t][2 * j + 1];
        K[t][2 * j]     = k0 * c - k1 * s;
        K[t][2 * j + 1] = k1 * c + k0 * s;
    }
    __syncthreads();

    for (int idx = tid; idx < 32 * 32; idx += 128) {
        int tq = idx >> 5;
        int tk = idx & 31;
        float a = 0.f;
#pragma unroll
        for (int d = 0; d < 64; d++) a = fmaf(Q[tq][d], K[tk][d], a);
        S[tq][tk] = a * 0.125f;
    }
    __syncthreads();

    if (tid < 32) {
        int row = tid;
        float m = -1e30f;
        for (int k = 0; k <= row; k++) m = fmaxf(m, S[row][k]);
        float sum = 0.f;
        for (int k = 0; k <= row; k++) {
            float e = __expf(S[row][k] - m);
            S[row][k] = e;
            sum += e;
        }
        float inv = 1.0f / sum;
        for (int k = 0; k < 32; k++)
            S[row][k] = (k <= row) ? S[row][k] * inv : 0.f;
    }
    __syncthreads();

    for (int idx = tid; idx < 32 * 64; idx += 128) {
        int t = idx >> 6;
        int d = idx & 63;
        float a = 0.f;
#pragma unroll
        for (int k = 0; k < 32; k++) a = fmaf(S[t][k], V[k][d], a);
        o[(size_t)(base + t * TOK_TSTRIDE) * DIMD + head * HDIM + d] = f2tf32(a);
    }
}

// ---------------------------------------------------------------------------
// Launch
// ---------------------------------------------------------------------------
extern "C" void kernel_launch(void* const* d_in, const int* in_sizes, int n_in,
                              void* d_out, int out_size)
{
    const float* x     = (const float*)d_in[0];   // [NTOK, 1024]
    const float* w_qkv = (const float*)d_in[1];   // [3072, 1024]
    const float* w_out = (const float*)d_in[2];   // [1024, 1024]
    const float* b_out = (const float*)d_in[3];   // [1024]
    float* out = (float*)d_out;                   // [NTOK, 1024]

    float* qkv;   uint32_t* o;
    uint32_t* xt; uint32_t* wqt; uint32_t* wot;
    cudaGetSymbolAddress((void**)&qkv, g_qkv);
    cudaGetSymbolAddress((void**)&o,   g_o);
    cudaGetSymbolAddress((void**)&xt,  g_xt);
    cudaGetSymbolAddress((void**)&wqt, g_wqt);
    cudaGetSymbolAddress((void**)&wot, g_wot);

    cudaFuncSetAttribute(gemm_tf32, cudaFuncAttributeMaxDynamicSharedMemorySize, GSMEM_BYTES);

    // 0) Convert inputs to tf32 bits (rna)
    {
        int n4 = NTOK * DIMD / 4;
        cvt_tf32<<<(n4 + 255) / 256, 256>>>((const float4*)x, (uint4*)xt, n4);
        n4 = E3 * DIMD / 4;
        cvt_tf32<<<(n4 + 255) / 256, 256>>>((const float4*)w_qkv, (uint4*)wqt, n4);
        n4 = DIMD * DIMD / 4;
        cvt_tf32<<<(n4 + 255) / 256, 256>>>((const float4*)w_out, (uint4*)wot, n4);
    }

    // 1) QKV projection: [36864,1024] x [3072,1024]^T -> [36864,3072] (fp32 out)
    {
        dim3 grid(E3 / 128, NTOK / 128);
        gemm_tf32<<<grid, 128, GSMEM_BYTES>>>(xt, wqt, nullptr, qkv, NTOK, E3, DIMD);
    }

    // 2) Attention (writes tf32-bit output)
    {
        int nblocks = (BB * HH * WW) * NHEADS;   // 18432
        attn_kernel<<<nblocks, 128>>>(qkv, o);
    }

    // 3) Output projection: [36864,1024] x [1024,1024]^T + bias
    {
        dim3 grid(DIMD / 128, NTOK / 128);
        gemm_tf32<<<grid, 128, GSMEM_BYTES>>>(o, wot, b_out, out, NTOK, DIMD, DIMD);
    }
}